// round 1
// baseline (speedup 1.0000x reference)
#include <cuda_runtime.h>
#include <cstdint>

#define Dd 1024
#define Hh 1024
#define Bb 8
#define Nn 40
#define Ll 20
#define NF 320          // B*N  (f rows)
#define NV 160          // B*L  (v rows)
#define NPAIR_T 780     // N*(N-1)/2
#define NTEXT 6240      // B*780
#define TM 32
#define TNC 128
#define TK 32
#define NTHREADS 256

typedef unsigned long long ull;

// ---------- packed fp32 helpers (fp32 FFMA 3-reg is half rate on sm_10x; f32x2 restores it) ----------
__device__ __forceinline__ ull pack2(float x, float y) {
    ull r; asm("mov.b64 %0, {%1, %2};" : "=l"(r) : "f"(x), "f"(y)); return r;
}
__device__ __forceinline__ void fma2(ull& acc, ull a, ull b) {
    asm("fma.rn.f32x2 %0, %1, %2, %0;" : "+l"(acc) : "l"(a), "l"(b));
}
__device__ __forceinline__ float2 unpack2(ull a) {
    float2 r; asm("mov.b64 {%0, %1}, %2;" : "=f"(r.x), "=f"(r.y) : "l"(a)); return r;
}

// ---------- scratch (__device__ globals: allocation-free) ----------
__device__ float g_FWVW[(NF + NV) * Hh];   // rows 0..319: f@Wf ; rows 320..479: v@Ws
__device__ float g_S[64];

// =====================================================================
// FW/VW precompute: C[480][1024], C[g] = (g<320 ? f[g]@gW1[:D] : v[g-320]@gW1[D:2D])
// =====================================================================
__global__ __launch_bounds__(NTHREADS) void fwvw_kernel(
    const float* __restrict__ span, const float* __restrict__ img,
    const float* __restrict__ gW1)
{
    __shared__ float At[TK * 33];
    __shared__ float Wt[TK * TNC];
    const int g0 = blockIdx.x * TM;
    const int n0 = blockIdx.y * TNC;
    const int t = threadIdx.x, tx = t & 15, ty = t >> 4;
    const bool isv = (g0 >= NF);
    const float* Wsrc = gW1 + (isv ? (size_t)Dd * Hh : 0);

    ull acc[8] = {0,0,0,0,0,0,0,0};
    for (int kt = 0; kt < Dd / TK; ++kt) {
#pragma unroll
        for (int it = 0; it < 4; ++it) {
            int idx = t + it * 256; int k = idx & 31, r = idx >> 5;
            int g = g0 + r;
            const float* srow = isv ? (img + (size_t)(g - NF) * Dd) : (span + (size_t)g * Dd);
            At[k * 33 + r] = srow[kt * TK + k];
        }
#pragma unroll
        for (int it = 0; it < 4; ++it) {
            int idx = t + it * 256; int kk = idx >> 5, c4 = idx & 31;
            ((float4*)Wt)[kk * (TNC / 4) + c4] =
                *(const float4*)&Wsrc[(size_t)(kt * TK + kk) * Hh + n0 + c4 * 4];
        }
        __syncthreads();
#pragma unroll
        for (int k = 0; k < TK; ++k) {
            float a0s = At[k * 33 + 2 * ty], a1s = At[k * 33 + 2 * ty + 1];
            ull A0 = pack2(a0s, a0s), A1 = pack2(a1s, a1s);
            const ull* wrow = (const ull*)&Wt[k * TNC + tx * 8];
            ull w0 = wrow[0], w1 = wrow[1], w2 = wrow[2], w3 = wrow[3];
            fma2(acc[0], A0, w0); fma2(acc[1], A0, w1); fma2(acc[2], A0, w2); fma2(acc[3], A0, w3);
            fma2(acc[4], A1, w0); fma2(acc[5], A1, w1); fma2(acc[6], A1, w2); fma2(acc[7], A1, w3);
        }
        __syncthreads();
    }
#pragma unroll
    for (int dr = 0; dr < 2; ++dr) {
        int g = g0 + 2 * ty + dr;
#pragma unroll
        for (int cp = 0; cp < 4; ++cp) {
            float2 v = unpack2(acc[dr * 4 + cp]);
            int n = n0 + tx * 8 + cp * 2;
            g_FWVW[(size_t)g * Hh + n] = v.x;
            g_FWVW[(size_t)g * Hh + n + 1] = v.y;
        }
    }
}

// =====================================================================
// Fused grounding kernel: block = (i, 32 consecutive j). Computes
// h1 = relu(FW[i] + VW[j] + (f[i] o v[j])@Wp + b1) in smem, then
// score = relu(h1@W2+b2) . W3 + b3, masked, -> out_g[i*160 + j]
// =====================================================================
__global__ __launch_bounds__(NTHREADS) void ground_kernel(
    const float* __restrict__ span, const float* __restrict__ img,
    const float* __restrict__ smask, const float* __restrict__ imask,
    const float* __restrict__ gW1, const float* __restrict__ gb1,
    const float* __restrict__ gW2, const float* __restrict__ gb2,
    const float* __restrict__ gW3, const float* __restrict__ gb3,
    float* __restrict__ out_g)
{
    extern __shared__ float sm[];
    float* h1  = sm;                         // TM * 1025
    float* Wt  = h1 + TM * 1025;             // TK * TNC
    float* At  = Wt + TK * TNC;              // TK * 33
    float* ssc = At + TK * 33;               // TM

    const int bx = blockIdx.x;
    const int i  = bx / 5;
    const int j0 = (bx % 5) * TM;
    const int t = threadIdx.x, tx = t & 15, ty = t >> 4;
    const float* frow = span + (size_t)i * Dd;
    const float* Wp = gW1 + (size_t)2 * Dd * Hh;

    // ---------------- stage 1: h1 ----------------
    for (int c = 0; c < Hh / TNC; ++c) {
        const int n0 = c * TNC;
        ull acc[8] = {0,0,0,0,0,0,0,0};
        for (int kt = 0; kt < Dd / TK; ++kt) {
#pragma unroll
            for (int it = 0; it < 4; ++it) {
                int idx = t + it * 256; int k = idx & 31, r = idx >> 5;
                int kk = kt * TK + k;
                At[k * 33 + r] = frow[kk] * img[(size_t)(j0 + r) * Dd + kk];
            }
#pragma unroll
            for (int it = 0; it < 4; ++it) {
                int idx = t + it * 256; int kk = idx >> 5, c4 = idx & 31;
                ((float4*)Wt)[kk * (TNC / 4) + c4] =
                    *(const float4*)&Wp[(size_t)(kt * TK + kk) * Hh + n0 + c4 * 4];
            }
            __syncthreads();
#pragma unroll
            for (int k = 0; k < TK; ++k) {
                float a0s = At[k * 33 + 2 * ty], a1s = At[k * 33 + 2 * ty + 1];
                ull A0 = pack2(a0s, a0s), A1 = pack2(a1s, a1s);
                const ull* wrow = (const ull*)&Wt[k * TNC + tx * 8];
                ull w0 = wrow[0], w1 = wrow[1], w2 = wrow[2], w3 = wrow[3];
                fma2(acc[0], A0, w0); fma2(acc[1], A0, w1); fma2(acc[2], A0, w2); fma2(acc[3], A0, w3);
                fma2(acc[4], A1, w0); fma2(acc[5], A1, w1); fma2(acc[6], A1, w2); fma2(acc[7], A1, w3);
            }
            __syncthreads();
        }
        // epilogue: add FW, VW, b1; relu; store to smem h1
#pragma unroll
        for (int dr = 0; dr < 2; ++dr) {
            int r = 2 * ty + dr; int jv = j0 + r;
            const float* fw = g_FWVW + (size_t)i * Hh;
            const float* vw = g_FWVW + (size_t)(NF + jv) * Hh;
#pragma unroll
            for (int cp = 0; cp < 4; ++cp) {
                float2 v = unpack2(acc[dr * 4 + cp]);
                int n = n0 + tx * 8 + cp * 2;
                float x0 = v.x + fw[n] + vw[n] + gb1[n];
                float x1 = v.y + fw[n + 1] + vw[n + 1] + gb1[n + 1];
                h1[r * 1025 + n]     = fmaxf(x0, 0.f);
                h1[r * 1025 + n + 1] = fmaxf(x1, 0.f);
            }
        }
    }
    if (t < TM) ssc[t] = 0.f;
    __syncthreads();   // h1 complete + ssc zeroed

    // ---------------- stage 2: relu(h1@W2+b2) . W3 ----------------
    float scp0 = 0.f, scp1 = 0.f;
    for (int c = 0; c < Hh / TNC; ++c) {
        const int n0 = c * TNC;
        ull acc[8] = {0,0,0,0,0,0,0,0};
        for (int kt = 0; kt < Hh / TK; ++kt) {
#pragma unroll
            for (int it = 0; it < 4; ++it) {
                int idx = t + it * 256; int kk = idx >> 5, c4 = idx & 31;
                ((float4*)Wt)[kk * (TNC / 4) + c4] =
                    *(const float4*)&gW2[(size_t)(kt * TK + kk) * Hh + n0 + c4 * 4];
            }
            __syncthreads();
#pragma unroll
            for (int k = 0; k < TK; ++k) {
                int kk = kt * TK + k;
                float a0s = h1[(2 * ty) * 1025 + kk];
                float a1s = h1[(2 * ty + 1) * 1025 + kk];
                ull A0 = pack2(a0s, a0s), A1 = pack2(a1s, a1s);
                const ull* wrow = (const ull*)&Wt[k * TNC + tx * 8];
                ull w0 = wrow[0], w1 = wrow[1], w2 = wrow[2], w3 = wrow[3];
                fma2(acc[0], A0, w0); fma2(acc[1], A0, w1); fma2(acc[2], A0, w2); fma2(acc[3], A0, w3);
                fma2(acc[4], A1, w0); fma2(acc[5], A1, w1); fma2(acc[6], A1, w2); fma2(acc[7], A1, w3);
            }
            __syncthreads();
        }
#pragma unroll
        for (int dr = 0; dr < 2; ++dr) {
            float sp = 0.f;
#pragma unroll
            for (int cp = 0; cp < 4; ++cp) {
                float2 v = unpack2(acc[dr * 4 + cp]);
                int n = n0 + tx * 8 + cp * 2;
                sp += fmaxf(v.x + gb2[n], 0.f) * gW3[n];
                sp += fmaxf(v.y + gb2[n + 1], 0.f) * gW3[n + 1];
            }
            if (dr == 0) scp0 += sp; else scp1 += sp;
        }
    }
    atomicAdd(&ssc[2 * ty],     scp0);
    atomicAdd(&ssc[2 * ty + 1], scp1);
    __syncthreads();
    if (t < TM) {
        int jv = j0 + t;
        float m = smask[i] * imask[jv];
        out_g[(size_t)i * NV + jv] = (ssc[t] + gb3[0]) * m;
    }
}

// =====================================================================
// Fused text kernel: 32 pair-rows per block, K=3072 first layer.
// =====================================================================
__global__ __launch_bounds__(NTHREADS) void text_kernel(
    const float* __restrict__ span,
    const float* __restrict__ tW1, const float* __restrict__ tb1,
    const float* __restrict__ tW2, const float* __restrict__ tb2,
    const float* __restrict__ tW3, const float* __restrict__ tb3,
    float* __restrict__ out_t)
{
    extern __shared__ float sm[];
    float* h1  = sm;
    float* Wt  = h1 + TM * 1025;
    float* At  = Wt + TK * TNC;
    float* ssc = At + TK * 33;
    __shared__ int b_s[TM], fi_s[TM], si_s[TM];

    const int bx = blockIdx.x;
    const int t = threadIdx.x, tx = t & 15, ty = t >> 4;

    if (t < TM) {
        int R = bx * TM + t;
        int b = R / NPAIR_T, q = R % NPAIR_T;
        int fi = 0, cnt = Nn - 1, rem = q;
        while (rem >= cnt) { rem -= cnt; fi++; cnt--; }
        b_s[t] = b; fi_s[t] = fi; si_s[t] = fi + 1 + rem;
    }
    __syncthreads();

    // ---------------- stage 1 (K = 3072) ----------------
    for (int c = 0; c < Hh / TNC; ++c) {
        const int n0 = c * TNC;
        ull acc[8] = {0,0,0,0,0,0,0,0};
        for (int kt = 0; kt < (3 * Dd) / TK; ++kt) {
            const int region = (kt * TK) >> 10;
            const int dbase = (kt * TK) & 1023;
#pragma unroll
            for (int it = 0; it < 4; ++it) {
                int idx = t + it * 256; int k = idx & 31, r = idx >> 5;
                int d = dbase + k;
                const float* sb = span + (size_t)b_s[r] * Nn * Dd;
                float val;
                if (region == 0)      val = sb[(size_t)fi_s[r] * Dd + d];
                else if (region == 1) val = sb[(size_t)si_s[r] * Dd + d];
                else                  val = sb[(size_t)fi_s[r] * Dd + d] * sb[(size_t)si_s[r] * Dd + d];
                At[k * 33 + r] = val;
            }
#pragma unroll
            for (int it = 0; it < 4; ++it) {
                int idx = t + it * 256; int kk = idx >> 5, c4 = idx & 31;
                ((float4*)Wt)[kk * (TNC / 4) + c4] =
                    *(const float4*)&tW1[(size_t)(kt * TK + kk) * Hh + n0 + c4 * 4];
            }
            __syncthreads();
#pragma unroll
            for (int k = 0; k < TK; ++k) {
                float a0s = At[k * 33 + 2 * ty], a1s = At[k * 33 + 2 * ty + 1];
                ull A0 = pack2(a0s, a0s), A1 = pack2(a1s, a1s);
                const ull* wrow = (const ull*)&Wt[k * TNC + tx * 8];
                ull w0 = wrow[0], w1 = wrow[1], w2 = wrow[2], w3 = wrow[3];
                fma2(acc[0], A0, w0); fma2(acc[1], A0, w1); fma2(acc[2], A0, w2); fma2(acc[3], A0, w3);
                fma2(acc[4], A1, w0); fma2(acc[5], A1, w1); fma2(acc[6], A1, w2); fma2(acc[7], A1, w3);
            }
            __syncthreads();
        }
#pragma unroll
        for (int dr = 0; dr < 2; ++dr) {
            int r = 2 * ty + dr;
#pragma unroll
            for (int cp = 0; cp < 4; ++cp) {
                float2 v = unpack2(acc[dr * 4 + cp]);
                int n = n0 + tx * 8 + cp * 2;
                h1[r * 1025 + n]     = fmaxf(v.x + tb1[n], 0.f);
                h1[r * 1025 + n + 1] = fmaxf(v.y + tb1[n + 1], 0.f);
            }
        }
    }
    if (t < TM) ssc[t] = 0.f;
    __syncthreads();

    // ---------------- stage 2 ----------------
    float scp0 = 0.f, scp1 = 0.f;
    for (int c = 0; c < Hh / TNC; ++c) {
        const int n0 = c * TNC;
        ull acc[8] = {0,0,0,0,0,0,0,0};
        for (int kt = 0; kt < Hh / TK; ++kt) {
#pragma unroll
            for (int it = 0; it < 4; ++it) {
                int idx = t + it * 256; int kk = idx >> 5, c4 = idx & 31;
                ((float4*)Wt)[kk * (TNC / 4) + c4] =
                    *(const float4*)&tW2[(size_t)(kt * TK + kk) * Hh + n0 + c4 * 4];
            }
            __syncthreads();
#pragma unroll
            for (int k = 0; k < TK; ++k) {
                int kk = kt * TK + k;
                float a0s = h1[(2 * ty) * 1025 + kk];
                float a1s = h1[(2 * ty + 1) * 1025 + kk];
                ull A0 = pack2(a0s, a0s), A1 = pack2(a1s, a1s);
                const ull* wrow = (const ull*)&Wt[k * TNC + tx * 8];
                ull w0 = wrow[0], w1 = wrow[1], w2 = wrow[2], w3 = wrow[3];
                fma2(acc[0], A0, w0); fma2(acc[1], A0, w1); fma2(acc[2], A0, w2); fma2(acc[3], A0, w3);
                fma2(acc[4], A1, w0); fma2(acc[5], A1, w1); fma2(acc[6], A1, w2); fma2(acc[7], A1, w3);
            }
            __syncthreads();
        }
#pragma unroll
        for (int dr = 0; dr < 2; ++dr) {
            float sp = 0.f;
#pragma unroll
            for (int cp = 0; cp < 4; ++cp) {
                float2 v = unpack2(acc[dr * 4 + cp]);
                int n = n0 + tx * 8 + cp * 2;
                sp += fmaxf(v.x + tb2[n], 0.f) * tW3[n];
                sp += fmaxf(v.y + tb2[n + 1], 0.f) * tW3[n + 1];
            }
            if (dr == 0) scp0 += sp; else scp1 += sp;
        }
    }
    atomicAdd(&ssc[2 * ty],     scp0);
    atomicAdd(&ssc[2 * ty + 1], scp1);
    __syncthreads();
    if (t < TM) {
        int R = bx * TM + t;
        out_t[R] = ssc[t] + tb3[0];
    }
}

// =====================================================================
// S[k] = sum of 800 consecutive grounding scores (flat (B,B,N,L) blocks)
// =====================================================================
__global__ void sreduce_kernel(const float* __restrict__ gsc) {
    __shared__ float red[256];
    int k = blockIdx.x;
    float s = 0.f;
    for (int idx = threadIdx.x; idx < 800; idx += 256) s += gsc[k * 800 + idx];
    red[threadIdx.x] = s;
    __syncthreads();
    for (int st = 128; st > 0; st >>= 1) {
        if (threadIdx.x < st) red[threadIdx.x] += red[threadIdx.x + st];
        __syncthreads();
    }
    if (threadIdx.x == 0) g_S[k] = red[0];
}

// loss = -(2*sum(S) - 8*(sum row-lse + sum col-lse)) / 8
__global__ void loss_kernel(float* __restrict__ out) {
    if (threadIdx.x == 0) {
        float S[64];
        for (int k = 0; k < 64; ++k) S[k] = g_S[k];
        float lr = 0.f, lc = 0.f, tot = 0.f;
        for (int r = 0; r < 8; ++r) {
            float m = -1e30f;
            for (int c = 0; c < 8; ++c) m = fmaxf(m, S[r * 8 + c]);
            float e = 0.f;
            for (int c = 0; c < 8; ++c) e += expf(S[r * 8 + c] - m);
            lr += m + logf(e);
        }
        for (int c = 0; c < 8; ++c) {
            float m = -1e30f;
            for (int r = 0; r < 8; ++r) m = fmaxf(m, S[r * 8 + c]);
            float e = 0.f;
            for (int r = 0; r < 8; ++r) e += expf(S[r * 8 + c] - m);
            lc += m + logf(e);
        }
        for (int k = 0; k < 64; ++k) tot += S[k];
        out[0] = -(2.f * tot - 8.f * (lr + lc)) / 8.f;
    }
}

// =====================================================================
extern "C" void kernel_launch(void* const* d_in, const int* in_sizes, int n_in,
                              void* d_out, int out_size) {
    (void)in_sizes; (void)n_in; (void)out_size;
    const float* span  = (const float*)d_in[0];
    const float* img   = (const float*)d_in[1];
    const float* smask = (const float*)d_in[2];
    const float* imask = (const float*)d_in[3];
    const float* tW1 = (const float*)d_in[4];  const float* tb1 = (const float*)d_in[5];
    const float* tW2 = (const float*)d_in[6];  const float* tb2 = (const float*)d_in[7];
    const float* tW3 = (const float*)d_in[8];  const float* tb3 = (const float*)d_in[9];
    const float* gW1 = (const float*)d_in[10]; const float* gb1 = (const float*)d_in[11];
    const float* gW2 = (const float*)d_in[12]; const float* gb2 = (const float*)d_in[13];
    const float* gW3 = (const float*)d_in[14]; const float* gb3 = (const float*)d_in[15];
    float* out = (float*)d_out;

    const size_t smem = (size_t)(TM * 1025 + TK * TNC + TK * 33 + TM) * sizeof(float);
    cudaFuncSetAttribute(ground_kernel, cudaFuncAttributeMaxDynamicSharedMemorySize, (int)smem);
    cudaFuncSetAttribute(text_kernel,   cudaFuncAttributeMaxDynamicSharedMemorySize, (int)smem);

    dim3 gFW((NF + NV) / TM, Hh / TNC);
    fwvw_kernel<<<gFW, NTHREADS>>>(span, img, gW1);

    ground_kernel<<<NF * 5, NTHREADS, smem>>>(span, img, smask, imask,
                                              gW1, gb1, gW2, gb2, gW3, gb3, out + 1);

    text_kernel<<<NTEXT / TM, NTHREADS, smem>>>(span, tW1, tb1, tW2, tb2, tW3, tb3,
                                                out + 1 + NF * NV);

    sreduce_kernel<<<64, 256>>>(out + 1);
    loss_kernel<<<1, 32>>>(out);
}

// round 2
// speedup vs baseline: 3.7651x; 3.7651x over previous
#include <cuda_runtime.h>
#include <cstdint>

typedef unsigned long long ull;

#define ASTR 20   // A smem row stride (16 k + 4 pad floats)

// ---------- packed fp32 helpers ----------
__device__ __forceinline__ ull pack2(float x, float y) {
    ull r; asm("mov.b64 %0, {%1, %2};" : "=l"(r) : "f"(x), "f"(y)); return r;
}
__device__ __forceinline__ void fma2(ull& acc, ull a, ull b) {
    asm("fma.rn.f32x2 %0, %1, %2, %0;" : "+l"(acc) : "l"(a), "l"(b));
}
__device__ __forceinline__ float2 unpack2(ull a) {
    float2 r; asm("mov.b64 {%0, %1}, %2;" : "=f"(r.x), "=f"(r.y) : "l"(a)); return r;
}
__device__ __forceinline__ uint32_t su32(const void* p) {
    uint32_t a;
    asm("{ .reg .u64 t; cvta.to.shared.u64 t, %1; cvt.u32.u64 %0, t; }" : "=r"(a) : "l"(p));
    return a;
}
__device__ __forceinline__ void cpasync16(uint32_t saddr, const void* g) {
    asm volatile("cp.async.cg.shared.global [%0], [%1], 16;" :: "r"(saddr), "l"(g));
}
#define CP_COMMIT asm volatile("cp.async.commit_group;")
#define CP_WAIT0  asm volatile("cp.async.wait_group 0;")

// ---------- scratch ----------
__device__ float g_FWVW[480 * 1024];
__device__ float g_h1[(size_t)51200 * 1024];
__device__ float g_h1t[(size_t)6240 * 1024];
__device__ float g_part[51200 * 8];
__device__ float g_partt[6240 * 8];
__device__ float g_S[64];

// =====================================================================
// FW/VW precompute (round-1 kernel, unchanged: 480x1024 = f@Wf / v@Ws)
// =====================================================================
__global__ __launch_bounds__(256) void fwvw_kernel(
    const float* __restrict__ span, const float* __restrict__ img,
    const float* __restrict__ gW1)
{
    __shared__ float At[32 * 33];
    __shared__ float Wt[32 * 128];
    const int g0 = blockIdx.x * 32;
    const int n0 = blockIdx.y * 128;
    const int t = threadIdx.x, tx = t & 15, ty = t >> 4;
    const bool isv = (g0 >= 320);
    const float* Wsrc = gW1 + (isv ? (size_t)1024 * 1024 : 0);

    ull acc[8] = {0,0,0,0,0,0,0,0};
    for (int kt = 0; kt < 32; ++kt) {
#pragma unroll
        for (int it = 0; it < 4; ++it) {
            int idx = t + it * 256; int k = idx & 31, r = idx >> 5;
            int g = g0 + r;
            const float* srow = isv ? (img + (size_t)(g - 320) * 1024) : (span + (size_t)g * 1024);
            At[k * 33 + r] = srow[kt * 32 + k];
        }
#pragma unroll
        for (int it = 0; it < 4; ++it) {
            int idx = t + it * 256; int kk = idx >> 5, c4 = idx & 31;
            ((float4*)Wt)[kk * 32 + c4] =
                *(const float4*)&Wsrc[(size_t)(kt * 32 + kk) * 1024 + n0 + c4 * 4];
        }
        __syncthreads();
#pragma unroll
        for (int k = 0; k < 32; ++k) {
            float a0s = At[k * 33 + 2 * ty], a1s = At[k * 33 + 2 * ty + 1];
            ull A0 = pack2(a0s, a0s), A1 = pack2(a1s, a1s);
            const ull* wrow = (const ull*)&Wt[k * 128 + tx * 8];
            ull w0 = wrow[0], w1 = wrow[1], w2 = wrow[2], w3 = wrow[3];
            fma2(acc[0], A0, w0); fma2(acc[1], A0, w1); fma2(acc[2], A0, w2); fma2(acc[3], A0, w3);
            fma2(acc[4], A1, w0); fma2(acc[5], A1, w1); fma2(acc[6], A1, w2); fma2(acc[7], A1, w3);
        }
        __syncthreads();
    }
#pragma unroll
    for (int dr = 0; dr < 2; ++dr) {
        int g = g0 + 2 * ty + dr;
#pragma unroll
        for (int cp = 0; cp < 4; ++cp) {
            float2 v = unpack2(acc[dr * 4 + cp]);
            int n = n0 + tx * 8 + cp * 2;
            g_FWVW[(size_t)g * 1024 + n] = v.x;
            g_FWVW[(size_t)g * 1024 + n + 1] = v.y;
        }
    }
}

// =====================================================================
// Shared GEMM micro-kernel pieces (128x128x16 tile, 256 thr, 8x8/thread)
// thread map: w=t>>5, l=t&31; wr=w&3 (32 rows), wc=w>>2 (64 cols)
//             lane_r=l&3, lane_c=l>>2; rows rbase+4m, cols coff+0..7
// =====================================================================
#define GEMM_IDX                                                     \
    const int t = threadIdx.x, l = t & 31, w = t >> 5;               \
    const int wr = w & 3, wc = w >> 2;                               \
    const int lane_r = l & 3, lane_c = l >> 2;                       \
    const int coff = wc * 64 + lane_c * 8;                           \
    const int rbase = wr * 32 + lane_r;

__device__ __forceinline__ void compute_tile(
    const float* __restrict__ Ac, const float* __restrict__ Bc,
    ull acc[8][4], int rbase, int coff)
{
#pragma unroll
    for (int k = 0; k < 16; ++k) {
        const ull* bp = (const ull*)&Bc[k * 128 + coff];
        ull b0 = bp[0], b1 = bp[1], b2 = bp[2], b3 = bp[3];
#pragma unroll
        for (int m = 0; m < 8; ++m) {
            float a = Ac[(rbase + 4 * m) * ASTR + k];
            ull a2 = pack2(a, a);
            fma2(acc[m][0], a2, b0); fma2(acc[m][1], a2, b1);
            fma2(acc[m][2], a2, b2); fma2(acc[m][3], a2, b3);
        }
    }
}

// =====================================================================
// Grounding GEMM1: h1 = relu((f o v) @ Wp + FW[i] + VW[j] + b1)
// =====================================================================
__global__ __launch_bounds__(256, 2) void g_gemm1(
    const float* __restrict__ span, const float* __restrict__ img,
    const float* __restrict__ gW1, const float* __restrict__ gb1)
{
    __shared__ float As[2][128 * ASTR];
    __shared__ float Bs[2][16 * 128];
    GEMM_IDX;
    const int n0 = blockIdx.x * 128, p0 = blockIdx.y * 128;
    const float* Wp = gW1 + (size_t)2 * 1024 * 1024;

    // A-gen setup: thread owns k=kk for 8 rows rg*8+e
    const int kk = t & 15, rg = t >> 4;
    int off_f[8], off_v[8];
#pragma unroll
    for (int e = 0; e < 8; ++e) {
        int p = p0 + rg * 8 + e;
        int i = p / 160, j = p - i * 160;
        off_f[e] = i * 1024 + kk;
        off_v[e] = j * 1024 + kk;
    }
    const int bkk = t >> 5, bc4 = t & 31;   // B: 2 float4 per thread

    // prologue: tile 0
    {
#pragma unroll
        for (int e = 0; e < 8; ++e)
            As[0][(rg * 8 + e) * ASTR + kk] = span[off_f[e]] * img[off_v[e]];
        cpasync16(su32(&Bs[0][bkk * 128 + bc4 * 4]),       Wp + (size_t)bkk * 1024 + n0 + bc4 * 4);
        cpasync16(su32(&Bs[0][(bkk + 8) * 128 + bc4 * 4]), Wp + (size_t)(bkk + 8) * 1024 + n0 + bc4 * 4);
        CP_COMMIT;
    }
    ull acc[8][4];
#pragma unroll
    for (int m = 0; m < 8; ++m) { acc[m][0]=0; acc[m][1]=0; acc[m][2]=0; acc[m][3]=0; }

    for (int kt = 0; kt < 64; ++kt) {
        CP_WAIT0; __syncthreads();
        const float* Ac = As[kt & 1];
        const float* Bc = Bs[kt & 1];
        float av[8];
        const bool nxt = (kt < 63);
        if (nxt) {
            int k0n = (kt + 1) * 16;
#pragma unroll
            for (int e = 0; e < 8; ++e)
                av[e] = span[off_f[e] + k0n] * img[off_v[e] + k0n];
            float* Bn = Bs[(kt + 1) & 1];
            cpasync16(su32(&Bn[bkk * 128 + bc4 * 4]),       Wp + (size_t)(k0n + bkk) * 1024 + n0 + bc4 * 4);
            cpasync16(su32(&Bn[(bkk + 8) * 128 + bc4 * 4]), Wp + (size_t)(k0n + bkk + 8) * 1024 + n0 + bc4 * 4);
        }
        compute_tile(Ac, Bc, acc, rbase, coff);
        if (nxt) {
            float* An = As[(kt + 1) & 1];
#pragma unroll
            for (int e = 0; e < 8; ++e) An[(rg * 8 + e) * ASTR + kk] = av[e];
            CP_COMMIT;
        }
    }
    // epilogue
    float bias[8];
#pragma unroll
    for (int q = 0; q < 8; ++q) bias[q] = gb1[n0 + coff + q];
#pragma unroll
    for (int m = 0; m < 8; ++m) {
        int r = rbase + 4 * m, p = p0 + r;
        int i = p / 160, j = p - i * 160;
        const float* fw = g_FWVW + (size_t)i * 1024 + n0 + coff;
        const float* vw = g_FWVW + (size_t)(320 + j) * 1024 + n0 + coff;
        float o[8];
#pragma unroll
        for (int q = 0; q < 4; ++q) {
            float2 xy = unpack2(acc[m][q]);
            o[2*q]   = fmaxf(xy.x + fw[2*q]   + vw[2*q]   + bias[2*q],   0.f);
            o[2*q+1] = fmaxf(xy.y + fw[2*q+1] + vw[2*q+1] + bias[2*q+1], 0.f);
        }
        float4* dst = (float4*)&g_h1[(size_t)p * 1024 + n0 + coff];
        dst[0] = make_float4(o[0], o[1], o[2], o[3]);
        dst[1] = make_float4(o[4], o[5], o[6], o[7]);
    }
}

// =====================================================================
// Grounding GEMM2: partial[p][nb] = sum_c relu(h1@W2 + b2)[c] * W3[c]
// =====================================================================
__global__ __launch_bounds__(256, 2) void g_gemm2(
    const float* __restrict__ gW2, const float* __restrict__ gb2,
    const float* __restrict__ gW3)
{
    __shared__ float As[2][128 * ASTR];
    __shared__ float Bs[2][16 * 128];
    __shared__ float red[2][128];
    GEMM_IDX;
    const int n0 = blockIdx.x * 128, p0 = blockIdx.y * 128;
    const int ar0 = t >> 2, ak0 = t & 3;     // A: 2 float4 per thread
    const int bkk = t >> 5, bc4 = t & 31;

    {
        cpasync16(su32(&As[0][ar0 * ASTR + ak0 * 4]),        &g_h1[(size_t)(p0 + ar0) * 1024 + ak0 * 4]);
        cpasync16(su32(&As[0][(ar0 + 64) * ASTR + ak0 * 4]), &g_h1[(size_t)(p0 + ar0 + 64) * 1024 + ak0 * 4]);
        cpasync16(su32(&Bs[0][bkk * 128 + bc4 * 4]),       gW2 + (size_t)bkk * 1024 + n0 + bc4 * 4);
        cpasync16(su32(&Bs[0][(bkk + 8) * 128 + bc4 * 4]), gW2 + (size_t)(bkk + 8) * 1024 + n0 + bc4 * 4);
        CP_COMMIT;
    }
    ull acc[8][4];
#pragma unroll
    for (int m = 0; m < 8; ++m) { acc[m][0]=0; acc[m][1]=0; acc[m][2]=0; acc[m][3]=0; }

    for (int kt = 0; kt < 64; ++kt) {
        CP_WAIT0; __syncthreads();
        const float* Ac = As[kt & 1];
        const float* Bc = Bs[kt & 1];
        const bool nxt = (kt < 63);
        if (nxt) {
            int k0n = (kt + 1) * 16;
            float* An = As[(kt + 1) & 1];
            float* Bn = Bs[(kt + 1) & 1];
            cpasync16(su32(&An[ar0 * ASTR + ak0 * 4]),        &g_h1[(size_t)(p0 + ar0) * 1024 + k0n + ak0 * 4]);
            cpasync16(su32(&An[(ar0 + 64) * ASTR + ak0 * 4]), &g_h1[(size_t)(p0 + ar0 + 64) * 1024 + k0n + ak0 * 4]);
            cpasync16(su32(&Bn[bkk * 128 + bc4 * 4]),       gW2 + (size_t)(k0n + bkk) * 1024 + n0 + bc4 * 4);
            cpasync16(su32(&Bn[(bkk + 8) * 128 + bc4 * 4]), gW2 + (size_t)(k0n + bkk + 8) * 1024 + n0 + bc4 * 4);
        }
        compute_tile(Ac, Bc, acc, rbase, coff);
        if (nxt) CP_COMMIT;
    }
    float b2r[8], w3r[8];
#pragma unroll
    for (int q = 0; q < 8; ++q) { b2r[q] = gb2[n0 + coff + q]; w3r[q] = gW3[n0 + coff + q]; }
#pragma unroll
    for (int m = 0; m < 8; ++m) {
        float s = 0.f;
#pragma unroll
        for (int q = 0; q < 4; ++q) {
            float2 xy = unpack2(acc[m][q]);
            s += fmaxf(xy.x + b2r[2*q],   0.f) * w3r[2*q];
            s += fmaxf(xy.y + b2r[2*q+1], 0.f) * w3r[2*q+1];
        }
        s += __shfl_xor_sync(0xffffffffu, s, 4);
        s += __shfl_xor_sync(0xffffffffu, s, 8);
        s += __shfl_xor_sync(0xffffffffu, s, 16);
        if (l < 4) red[wc][rbase + 4 * m] = s;
    }
    __syncthreads();
    if (t < 128)
        g_part[(size_t)(p0 + t) * 8 + blockIdx.x] = red[0][t] + red[1][t];
}

// =====================================================================
// Text GEMM1: h1t = relu([f,s,f*s] @ tW1 + b1), K = 3072
// =====================================================================
__global__ __launch_bounds__(256, 2) void t_gemm1(
    const float* __restrict__ span,
    const float* __restrict__ tW1, const float* __restrict__ tb1)
{
    __shared__ float As[2][128 * ASTR];
    __shared__ float Bs[2][16 * 128];
    GEMM_IDX;
    const int n0 = blockIdx.x * 128, p0 = blockIdx.y * 128;

    const int kk = t & 15, rg = t >> 4;
    int off_a[8], off_b[8];
#pragma unroll
    for (int e = 0; e < 8; ++e) {
        int p = p0 + rg * 8 + e;
        int R = p < 6240 ? p : 6239;
        int b = R / 780, q = R - b * 780;
        int fi = 0, cnt = 39, rem = q;
        while (rem >= cnt) { rem -= cnt; fi++; cnt--; }
        int si = fi + 1 + rem;
        off_a[e] = (b * 40 + fi) * 1024 + kk;
        off_b[e] = (b * 40 + si) * 1024 + kk;
    }
    const int bkk = t >> 5, bc4 = t & 31;

    // A-gen for tile kt
    auto agen = [&](int k0, float av[8]) {
        int region = k0 >> 10;
        int dbase = k0 & 1023;
#pragma unroll
        for (int e = 0; e < 8; ++e) {
            float a = span[off_a[e] + dbase];
            float bval = span[off_b[e] + dbase];
            av[e] = (region == 0) ? a : (region == 1) ? bval : a * bval;
        }
    };

    {
        float av[8]; agen(0, av);
#pragma unroll
        for (int e = 0; e < 8; ++e) As[0][(rg * 8 + e) * ASTR + kk] = av[e];
        cpasync16(su32(&Bs[0][bkk * 128 + bc4 * 4]),       tW1 + (size_t)bkk * 1024 + n0 + bc4 * 4);
        cpasync16(su32(&Bs[0][(bkk + 8) * 128 + bc4 * 4]), tW1 + (size_t)(bkk + 8) * 1024 + n0 + bc4 * 4);
        CP_COMMIT;
    }
    ull acc[8][4];
#pragma unroll
    for (int m = 0; m < 8; ++m) { acc[m][0]=0; acc[m][1]=0; acc[m][2]=0; acc[m][3]=0; }

    for (int kt = 0; kt < 192; ++kt) {
        CP_WAIT0; __syncthreads();
        const float* Ac = As[kt & 1];
        const float* Bc = Bs[kt & 1];
        float av[8];
        const bool nxt = (kt < 191);
        if (nxt) {
            int k0n = (kt + 1) * 16;
            agen(k0n, av);
            float* Bn = Bs[(kt + 1) & 1];
            cpasync16(su32(&Bn[bkk * 128 + bc4 * 4]),       tW1 + (size_t)(k0n + bkk) * 1024 + n0 + bc4 * 4);
            cpasync16(su32(&Bn[(bkk + 8) * 128 + bc4 * 4]), tW1 + (size_t)(k0n + bkk + 8) * 1024 + n0 + bc4 * 4);
        }
        compute_tile(Ac, Bc, acc, rbase, coff);
        if (nxt) {
            float* An = As[(kt + 1) & 1];
#pragma unroll
            for (int e = 0; e < 8; ++e) An[(rg * 8 + e) * ASTR + kk] = av[e];
            CP_COMMIT;
        }
    }
    float bias[8];
#pragma unroll
    for (int q = 0; q < 8; ++q) bias[q] = tb1[n0 + coff + q];
#pragma unroll
    for (int m = 0; m < 8; ++m) {
        int r = rbase + 4 * m, p = p0 + r;
        if (p >= 6240) continue;
        float o[8];
#pragma unroll
        for (int q = 0; q < 4; ++q) {
            float2 xy = unpack2(acc[m][q]);
            o[2*q]   = fmaxf(xy.x + bias[2*q],   0.f);
            o[2*q+1] = fmaxf(xy.y + bias[2*q+1], 0.f);
        }
        float4* dst = (float4*)&g_h1t[(size_t)p * 1024 + n0 + coff];
        dst[0] = make_float4(o[0], o[1], o[2], o[3]);
        dst[1] = make_float4(o[4], o[5], o[6], o[7]);
    }
}

// =====================================================================
// Text GEMM2
// =====================================================================
__global__ __launch_bounds__(256, 2) void t_gemm2(
    const float* __restrict__ tW2, const float* __restrict__ tb2,
    const float* __restrict__ tW3)
{
    __shared__ float As[2][128 * ASTR];
    __shared__ float Bs[2][16 * 128];
    __shared__ float red[2][128];
    GEMM_IDX;
    const int n0 = blockIdx.x * 128, p0 = blockIdx.y * 128;
    const int ar0 = t >> 2, ak0 = t & 3;
    const int bkk = t >> 5, bc4 = t & 31;
    const int r0c = (p0 + ar0)      < 6240 ? (p0 + ar0)      : 6239;
    const int r1c = (p0 + ar0 + 64) < 6240 ? (p0 + ar0 + 64) : 6239;

    {
        cpasync16(su32(&As[0][ar0 * ASTR + ak0 * 4]),        &g_h1t[(size_t)r0c * 1024 + ak0 * 4]);
        cpasync16(su32(&As[0][(ar0 + 64) * ASTR + ak0 * 4]), &g_h1t[(size_t)r1c * 1024 + ak0 * 4]);
        cpasync16(su32(&Bs[0][bkk * 128 + bc4 * 4]),       tW2 + (size_t)bkk * 1024 + n0 + bc4 * 4);
        cpasync16(su32(&Bs[0][(bkk + 8) * 128 + bc4 * 4]), tW2 + (size_t)(bkk + 8) * 1024 + n0 + bc4 * 4);
        CP_COMMIT;
    }
    ull acc[8][4];
#pragma unroll
    for (int m = 0; m < 8; ++m) { acc[m][0]=0; acc[m][1]=0; acc[m][2]=0; acc[m][3]=0; }

    for (int kt = 0; kt < 64; ++kt) {
        CP_WAIT0; __syncthreads();
        const float* Ac = As[kt & 1];
        const float* Bc = Bs[kt & 1];
        const bool nxt = (kt < 63);
        if (nxt) {
            int k0n = (kt + 1) * 16;
            float* An = As[(kt + 1) & 1];
            float* Bn = Bs[(kt + 1) & 1];
            cpasync16(su32(&An[ar0 * ASTR + ak0 * 4]),        &g_h1t[(size_t)r0c * 1024 + k0n + ak0 * 4]);
            cpasync16(su32(&An[(ar0 + 64) * ASTR + ak0 * 4]), &g_h1t[(size_t)r1c * 1024 + k0n + ak0 * 4]);
            cpasync16(su32(&Bn[bkk * 128 + bc4 * 4]),       tW2 + (size_t)(k0n + bkk) * 1024 + n0 + bc4 * 4);
            cpasync16(su32(&Bn[(bkk + 8) * 128 + bc4 * 4]), tW2 + (size_t)(k0n + bkk + 8) * 1024 + n0 + bc4 * 4);
        }
        compute_tile(Ac, Bc, acc, rbase, coff);
        if (nxt) CP_COMMIT;
    }
    float b2r[8], w3r[8];
#pragma unroll
    for (int q = 0; q < 8; ++q) { b2r[q] = tb2[n0 + coff + q]; w3r[q] = tW3[n0 + coff + q]; }
#pragma unroll
    for (int m = 0; m < 8; ++m) {
        float s = 0.f;
#pragma unroll
        for (int q = 0; q < 4; ++q) {
            float2 xy = unpack2(acc[m][q]);
            s += fmaxf(xy.x + b2r[2*q],   0.f) * w3r[2*q];
            s += fmaxf(xy.y + b2r[2*q+1], 0.f) * w3r[2*q+1];
        }
        s += __shfl_xor_sync(0xffffffffu, s, 4);
        s += __shfl_xor_sync(0xffffffffu, s, 8);
        s += __shfl_xor_sync(0xffffffffu, s, 16);
        if (l < 4) red[wc][rbase + 4 * m] = s;
    }
    __syncthreads();
    if (t < 128 && p0 + t < 6240)
        g_partt[(size_t)(p0 + t) * 8 + blockIdx.x] = red[0][t] + red[1][t];
}

// =====================================================================
// Finalize + reductions
// =====================================================================
__global__ void fin_g(const float* __restrict__ smask, const float* __restrict__ imask,
                      const float* __restrict__ gb3, float* __restrict__ out_g)
{
    int p = blockIdx.x * 256 + threadIdx.x;
    float s = gb3[0];
#pragma unroll
    for (int nb = 0; nb < 8; ++nb) s += g_part[(size_t)p * 8 + nb];
    int i = p / 160, j = p - i * 160;
    out_g[p] = s * (smask[i] * imask[j]);
}

__global__ void fin_t(const float* __restrict__ tb3, float* __restrict__ out_t)
{
    int p = blockIdx.x * 256 + threadIdx.x;
    if (p >= 6240) return;
    float s = tb3[0];
#pragma unroll
    for (int nb = 0; nb < 8; ++nb) s += g_partt[(size_t)p * 8 + nb];
    out_t[p] = s;
}

__global__ void sreduce_kernel(const float* __restrict__ gsc) {
    __shared__ float red[256];
    int k = blockIdx.x;
    float s = 0.f;
    for (int idx = threadIdx.x; idx < 800; idx += 256) s += gsc[k * 800 + idx];
    red[threadIdx.x] = s;
    __syncthreads();
    for (int st = 128; st > 0; st >>= 1) {
        if (threadIdx.x < st) red[threadIdx.x] += red[threadIdx.x + st];
        __syncthreads();
    }
    if (threadIdx.x == 0) g_S[k] = red[0];
}

__global__ void loss_kernel(float* __restrict__ out) {
    if (threadIdx.x == 0) {
        float S[64];
        for (int k = 0; k < 64; ++k) S[k] = g_S[k];
        float lr = 0.f, lc = 0.f, tot = 0.f;
        for (int r = 0; r < 8; ++r) {
            float m = -1e30f;
            for (int c = 0; c < 8; ++c) m = fmaxf(m, S[r * 8 + c]);
            float e = 0.f;
            for (int c = 0; c < 8; ++c) e += expf(S[r * 8 + c] - m);
            lr += m + logf(e);
        }
        for (int c = 0; c < 8; ++c) {
            float m = -1e30f;
            for (int r = 0; r < 8; ++r) m = fmaxf(m, S[r * 8 + c]);
            float e = 0.f;
            for (int r = 0; r < 8; ++r) e += expf(S[r * 8 + c] - m);
            lc += m + logf(e);
        }
        for (int k = 0; k < 64; ++k) tot += S[k];
        out[0] = -(2.f * tot - 8.f * (lr + lc)) / 8.f;
    }
}

// =====================================================================
extern "C" void kernel_launch(void* const* d_in, const int* in_sizes, int n_in,
                              void* d_out, int out_size) {
    (void)in_sizes; (void)n_in; (void)out_size;
    const float* span  = (const float*)d_in[0];
    const float* img   = (const float*)d_in[1];
    const float* smask = (const float*)d_in[2];
    const float* imask = (const float*)d_in[3];
    const float* tW1 = (const float*)d_in[4];  const float* tb1 = (const float*)d_in[5];
    const float* tW2 = (const float*)d_in[6];  const float* tb2 = (const float*)d_in[7];
    const float* tW3 = (const float*)d_in[8];  const float* tb3 = (const float*)d_in[9];
    const float* gW1 = (const float*)d_in[10]; const float* gb1 = (const float*)d_in[11];
    const float* gW2 = (const float*)d_in[12]; const float* gb2 = (const float*)d_in[13];
    const float* gW3 = (const float*)d_in[14]; const float* gb3 = (const float*)d_in[15];
    float* out = (float*)d_out;

    fwvw_kernel<<<dim3(15, 8), 256>>>(span, img, gW1);
    g_gemm1<<<dim3(8, 400), 256>>>(span, img, gW1, gb1);
    g_gemm2<<<dim3(8, 400), 256>>>(gW2, gb2, gW3);
    t_gemm1<<<dim3(8, 49), 256>>>(span, tW1, tb1);
    t_gemm2<<<dim3(8, 49), 256>>>(tW2, tb2, tW3);
    fin_g<<<200, 256>>>(smask, imask, gb3, out + 1);
    fin_t<<<25, 256>>>(tb3, out + 1 + 51200);
    sreduce_kernel<<<64, 256>>>(out + 1);
    loss_kernel<<<1, 32>>>(out);
}